// round 10
// baseline (speedup 1.0000x reference)
#include <cuda_runtime.h>
#include <cuda_bf16.h>
#include <cstdint>

#define BATCH 128
#define CH    128
#define NN    170
#define TT    12
#define NP    176          // padded node pitch
#define SCP   172          // score smem pitch (bf16)

static __device__ __align__(16) unsigned g_EdB[BATCH * NN * (NP/2)];   // E_d^T bf16 pairs
static __device__ float g_Asum[NN * NN];
static __device__ int   g_ctr;

// k_emb smem: es bf16x2 [128][88]u32 + xs f32 [128][88] + stage f32 [4][1056]
#define SMEM_E ((11264 + 11264 + 4224) * 4)            // 107,008 B -> 2 CTA/SM
// k_adj smem: ed f32 [170][176] + sc bf16 [170][172]
#define SMEM_A  (NN * NP * 4 + NN * SCP * 2)           // 178,160 B

// ------------------------------------------------------- packed f32x2 helpers
typedef unsigned long long u64t;

__device__ __forceinline__ u64t splat2(float v) {
    u64t d; asm("mov.b64 %0, {%1, %1};" : "=l"(d) : "f"(v)); return d;
}
__device__ __forceinline__ u64t splat2u(unsigned v) {     // f32 bits in u32
    u64t d; asm("mov.b64 %0, {%1, %1};" : "=l"(d) : "r"(v)); return d;
}
__device__ __forceinline__ void ffma2(u64t& c, u64t a, u64t b) {
    asm("fma.rn.f32x2 %0, %1, %2, %3;" : "=l"(c) : "l"(a), "l"(b), "l"(c));
}
__device__ __forceinline__ void unpack2(float& lo, float& hi, u64t v) {
    asm("mov.b64 {%0, %1}, %2;" : "=f"(lo), "=f"(hi) : "l"(v));
}
__device__ __forceinline__ float tanh_ap(float x) {
    float r; asm("tanh.approx.f32 %0, %1;" : "=f"(r) : "f"(x)); return r;
}
__device__ __forceinline__ float bf_lo(unsigned w) { return __uint_as_float(w << 16); }
__device__ __forceinline__ float bf_hi(unsigned w) { return __uint_as_float(w & 0xFFFF0000u); }
__device__ __forceinline__ unsigned bf_pack(float a, float b) {
    __nv_bfloat162 h = __floats2bfloat162_rn(a, b);
    return *reinterpret_cast<unsigned*>(&h);
}

// ---------- K_emb: fused coalesced x staging + t-reduce + GEMM1 + tanh (8x8)
// grid (128 batches, 2 n-halves), 256 threads, 2 CTA/SM.
__global__ void __launch_bounds__(256, 2) k_emb(const float* __restrict__ x,
                                                const float* __restrict__ Es) {
    extern __shared__ float smf[];
    unsigned* es = reinterpret_cast<unsigned*>(smf);   // bf16x2 [128][88]
    float* xs = smf + 11264;                           // f32 [128][88]
    float* stage = smf + 22528;                        // f32 [4][1056]
    const int tid = threadIdx.x;
    const int b = blockIdx.x, h = blockIdx.y;

    // stage Es as packed bf16 pairs: es[c][mp] = {Es[c][2mp], Es[c][2mp+1]}
    for (int i = tid; i < CH * 88; i += 256) {
        int c = i / 88, mp = i - c * 88;
        int m0 = mp * 2;
        float f0 = 0.f, f1 = 0.f;
        if (m0 < NN) {
            float2 e = *reinterpret_cast<const float2*>(Es + c * NN + m0);
            f0 = e.x; f1 = e.y;
        }
        es[i] = bf_pack(f0, f1);
    }

    // ---- coalesced x staging + t-reduction, 32 chunks of 4 channels
    const int len4 = h ? 246 : 264;                    // f4 per channel row
    const int nout = h ? 82 : 88;                      // valid n per channel
    const float* xbase = x + (size_t)b * (CH * NN * TT) + (size_t)h * 1056;
    for (int cc = 0; cc < 32; cc++) {
        // coalesced load: 4 channel rows of len4 float4 each
        for (int idx = tid; idx < 4 * len4; idx += 256) {
            int c = idx / len4, q = idx - c * len4;
            reinterpret_cast<float4*>(stage)[c * 264 + q] =
                __ldcs(reinterpret_cast<const float4*>(
                           xbase + (size_t)(cc * 4 + c) * (NN * TT)) + q);
        }
        __syncthreads();
        // reduce 12-float groups out of smem
        for (int i = tid; i < 4 * 88; i += 256) {
            int c = i >> 6 >> 2;  // placeholder; recomputed below
            c = i / 88;
            int n = i - c * 88;
            float s = 0.0f;
            if (n < nout) {
                const float4* pp = reinterpret_cast<const float4*>(
                    stage + c * 1056 + n * TT);
                float4 v0 = pp[0], v1 = pp[1], v2 = pp[2];
                s = ((v0.x + v0.y) + (v0.z + v0.w))
                  + ((v1.x + v1.y) + (v1.z + v1.w))
                  + ((v2.x + v2.y) + (v2.z + v2.w));
            }
            xs[(cc * 4 + c) * 88 + n] = s;
        }
        __syncthreads();
    }

    // ---- GEMM1: 22 m-strips(8) x 11 n-strips(8) = 242 cells, 1 per thread
    const int cell = tid;
    if (cell < 242) {
        const int smi = cell / 11, snj = cell - smi * 11;
        const int am = smi * 8, bn = snj * 8;
        u64t acc[8][4];
        #pragma unroll
        for (int i = 0; i < 8; i++)
            #pragma unroll
            for (int j = 0; j < 4; j++) acc[i][j] = 0ull;

        const unsigned* ep = es + (am >> 1);
        const float* bp = xs + bn;
        #pragma unroll 2
        for (int c = 0; c < CH; c++) {
            uint4 ev = *reinterpret_cast<const uint4*>(ep + c * 88);
            ulonglong2 b01 = *reinterpret_cast<const ulonglong2*>(bp + c * 88);
            ulonglong2 b23 = *reinterpret_cast<const ulonglong2*>(bp + c * 88 + 4);
            unsigned ew[4] = {ev.x, ev.y, ev.z, ev.w};
            #pragma unroll
            for (int q = 0; q < 4; q++) {
                u64t s0 = splat2u(ew[q] << 16);
                u64t s1 = splat2u(ew[q] & 0xFFFF0000u);
                ffma2(acc[2*q][0], s0, b01.x);  ffma2(acc[2*q][1], s0, b01.y);
                ffma2(acc[2*q][2], s0, b23.x);  ffma2(acc[2*q][3], s0, b23.y);
                ffma2(acc[2*q+1][0], s1, b01.x); ffma2(acc[2*q+1][1], s1, b01.y);
                ffma2(acc[2*q+1][2], s1, b23.x); ffma2(acc[2*q+1][3], s1, b23.y);
            }
        }

        // epilogue: tanh -> bf16 pairs -> g_EdB
        #pragma unroll
        for (int mi = 0; mi < 8; mi++) {
            int m = am + mi;
            if (m < NN) {
                float f[8];
                #pragma unroll
                for (int j = 0; j < 4; j++) unpack2(f[2*j], f[2*j+1], acc[mi][j]);
                uint4 o;
                o.x = bf_pack(tanh_ap(f[0]), tanh_ap(f[1]));
                o.y = bf_pack(tanh_ap(f[2]), tanh_ap(f[3]));
                o.z = bf_pack(tanh_ap(f[4]), tanh_ap(f[5]));
                o.w = bf_pack(tanh_ap(f[6]), tanh_ap(f[7]));
                unsigned* dst = g_EdB + ((size_t)b * NN + m) * (NP/2) + ((88*h + bn) >> 1);
                *reinterpret_cast<uint4*>(dst) = o;
            }
        }
    }
}

// --- K_adj: symmetric GEMM2 + softmax + atomics; last CTA does the threshold
__global__ void __launch_bounds__(512, 1) k_adj(float* __restrict__ out) {
    extern __shared__ float sm[];
    float* ed = sm;                                          // [170][176] f32
    __nv_bfloat16* sc = reinterpret_cast<__nv_bfloat16*>(sm + NN * NP);
    const int tid = threadIdx.x;
    const int b = blockIdx.x;

    // copy-in: bf16 -> f32 expansion
    {
        const uint4* src = reinterpret_cast<const uint4*>(g_EdB + (size_t)b * NN * (NP/2));
        for (int i = tid; i < (NN * NP) / 8; i += 512) {
            uint4 v = src[i];
            float4 f0, f1;
            f0.x = bf_lo(v.x); f0.y = bf_hi(v.x); f0.z = bf_lo(v.y); f0.w = bf_hi(v.y);
            f1.x = bf_lo(v.z); f1.y = bf_hi(v.z); f1.z = bf_lo(v.w); f1.w = bf_hi(v.w);
            reinterpret_cast<float4*>(ed)[2*i]   = f0;
            reinterpret_cast<float4*>(ed)[2*i+1] = f1;
        }
    }
    __syncthreads();

    const float scale = 0.08838834764831843f;                // 1/sqrt(128)
    const int cell = tid;
    if (cell < 253) {
        int si = (int)((sqrtf(8.0f * (float)cell + 1.0f) - 1.0f) * 0.5f);
        while ((si + 1) * (si + 2) / 2 <= cell) si++;
        while (si * (si + 1) / 2 > cell) si--;
        const int sj = cell - si * (si + 1) / 2;
        const int n = si * 8, k = sj * 8;

        u64t acc[8][4];
        #pragma unroll
        for (int i = 0; i < 8; i++)
            #pragma unroll
            for (int j = 0; j < 4; j++) acc[i][j] = 0ull;

        #pragma unroll 2
        for (int m = 0; m < NN; m++) {
            const float* row = ed + m * NP;
            ulonglong2 a01 = *reinterpret_cast<const ulonglong2*>(row + n);
            ulonglong2 a23 = *reinterpret_cast<const ulonglong2*>(row + n + 4);
            float4 k0 = *reinterpret_cast<const float4*>(row + k);
            float4 k1 = *reinterpret_cast<const float4*>(row + k + 4);
            float kv[8] = {k0.x, k0.y, k0.z, k0.w, k1.x, k1.y, k1.z, k1.w};
            #pragma unroll
            for (int ki = 0; ki < 8; ki++) {
                u64t s = splat2(kv[ki]);
                ffma2(acc[ki][0], s, a01.x); ffma2(acc[ki][1], s, a01.y);
                ffma2(acc[ki][2], s, a23.x); ffma2(acc[ki][3], s, a23.y);
            }
        }

        #pragma unroll
        for (int ki = 0; ki < 8; ki++) {
            int kk = k + ki;
            if (kk >= NN) continue;
            #pragma unroll
            for (int j = 0; j < 4; j++) {
                float v0, v1;
                unpack2(v0, v1, acc[ki][j]);
                int n0 = n + 2 * j, n1 = n0 + 1;
                __nv_bfloat16 h0 = __float2bfloat16(fmaxf(0.0f, v0 * scale));
                __nv_bfloat16 h1 = __float2bfloat16(fmaxf(0.0f, v1 * scale));
                if (n0 < NN) { sc[n0 * SCP + kk] = h0; sc[kk * SCP + n0] = h0; }
                if (n1 < NN) { sc[n1 * SCP + kk] = h1; sc[kk * SCP + n1] = h1; }
            }
        }
    }
    __syncthreads();

    // row softmax (scores in [0,~15.1] -> no max pass) + atomic accumulate
    const int wid = tid >> 5, lane = tid & 31;
    for (int n = wid; n < NN; n += 16) {
        const __nv_bfloat16* row = sc + n * SCP;
        float ssum = 0.0f;
        for (int kq = lane; kq < NN; kq += 32)
            ssum += __expf(__bfloat162float(row[kq]));
        #pragma unroll
        for (int o = 16; o; o >>= 1)
            ssum += __shfl_xor_sync(0xffffffffu, ssum, o);
        float inv = 1.0f / ssum;
        for (int kq = lane; kq < NN; kq += 32)
            atomicAdd(&g_Asum[n * NN + kq],
                      __expf(__bfloat162float(row[kq])) * inv);
    }

    // ---- last-CTA threshold + reset (replaces k_thresh launch)
    __threadfence();
    __shared__ int is_last;
    if (tid == 0) is_last = (atomicAdd(&g_ctr, 1) == BATCH - 1);
    __syncthreads();
    if (is_last) {
        for (int i = tid; i < NN * NN; i += 512) {
            float v = __ldcg(&g_Asum[i]);
            out[i] = (v > 64.0f) ? 1.0f : 0.0f;              // mean > 0.5
            g_Asum[i] = 0.0f;                                // restore for replay
        }
        __syncthreads();
        if (tid == 0) g_ctr = 0;
    }
}

// ------------------------------------------------------------------- launcher
extern "C" void kernel_launch(void* const* d_in, const int* in_sizes, int n_in,
                              void* d_out, int out_size) {
    const float* x  = (const float*)d_in[0];   // [128,128,170,12] f32
    const float* Es = (const float*)d_in[1];   // [128,170] f32
    float* out = (float*)d_out;                // [170,170] f32

    cudaFuncSetAttribute(k_emb, cudaFuncAttributeMaxDynamicSharedMemorySize, SMEM_E);
    cudaFuncSetAttribute(k_adj, cudaFuncAttributeMaxDynamicSharedMemorySize, SMEM_A);

    dim3 ge(BATCH, 2);
    k_emb<<<ge, 256, SMEM_E>>>(x, Es);
    k_adj<<<BATCH, 512, SMEM_A>>>(out);
}

// round 11
// speedup vs baseline: 1.7181x; 1.7181x over previous
#include <cuda_runtime.h>
#include <cuda_bf16.h>
#include <cstdint>

#define BATCH 128
#define CH    128
#define TTNN  2785280      // BATCH*CH*NN elements
#define NN    170
#define TT    12
#define NP    176          // padded node pitch
#define SCP   172          // score smem pitch (bf16)

static __device__ __align__(16) float    g_xs[BATCH * CH * NP];        // t-reduced x
static __device__ __align__(16) unsigned g_EdB[BATCH * NN * (NP/2)];   // E_d^T bf16 pairs
static __device__ float g_Asum[NN * NN];

// k_gemm1 smem: es bf16-pairs [128][88 u32] + xs f32 [128][88]
#define SMEM_G1 ((11264 + 11264) * 4)                  // 90,112 B -> 2 CTA/SM
// k_adj smem: ed f32 [170][176] + sc bf16 [170][172]  (scratch overlays ed)
#define SMEM_A  (NN * NP * 4 + NN * SCP * 2)           // 178,160 B

// ------------------------------------------------------- packed f32x2 helpers
typedef unsigned long long u64t;

__device__ __forceinline__ u64t splat2(float v) {
    u64t d; asm("mov.b64 %0, {%1, %1};" : "=l"(d) : "f"(v)); return d;
}
__device__ __forceinline__ u64t splat2u(unsigned v) {
    u64t d; asm("mov.b64 %0, {%1, %1};" : "=l"(d) : "r"(v)); return d;
}
__device__ __forceinline__ void ffma2(u64t& c, u64t a, u64t b) {
    asm("fma.rn.f32x2 %0, %1, %2, %3;" : "=l"(c) : "l"(a), "l"(b), "l"(c));
}
__device__ __forceinline__ void add2(u64t& c, u64t a) {
    asm("add.rn.f32x2 %0, %1, %2;" : "=l"(c) : "l"(a), "l"(c));
}
__device__ __forceinline__ void unpack2(float& lo, float& hi, u64t v) {
    asm("mov.b64 {%0, %1}, %2;" : "=f"(lo), "=f"(hi) : "l"(v));
}
__device__ __forceinline__ float tanh_ap(float x) {
    float r; asm("tanh.approx.f32 %0, %1;" : "=f"(r) : "f"(x)); return r;
}
__device__ __forceinline__ float bf_lo(unsigned w) { return __uint_as_float(w << 16); }
__device__ __forceinline__ float bf_hi(unsigned w) { return __uint_as_float(w & 0xFFFF0000u); }
__device__ __forceinline__ unsigned bf_pack(float a, float b) {
    __nv_bfloat162 h = __floats2bfloat162_rn(a, b);
    return *reinterpret_cast<unsigned*>(&h);
}
__device__ __forceinline__ float f4sum(float4 v) {
    return (v.x + v.y) + (v.z + v.w);
}
// gather granule g (0..95) from per-thread partials p0/p1/p2 (slot = g>>5)
__device__ __forceinline__ float gran(float p0, float p1, float p2, int g) {
    int l = g & 31, sl = g >> 5;
    float v0 = __shfl_sync(0xffffffffu, p0, l);
    float v1 = __shfl_sync(0xffffffffu, p1, l);
    float v2 = __shfl_sync(0xffffffffu, p2, l);
    return sl == 0 ? v0 : (sl == 1 ? v1 : v2);
}

// ---------------- K_load: barrier-free shuffle-regroup t-reduction x -> g_xs
// warp chunk = 32 elements = 96 contiguous float4; 2 chunks per iteration.
__global__ void __launch_bounds__(256) k_load(const float* __restrict__ x) {
    const int gw = (blockIdx.x * 256 + threadIdx.x) >> 5;   // global warp id
    const int lane = threadIdx.x & 31;
    const int nwarps = gridDim.x * 8;

    // zero pad columns of g_xs (np in [170,176))
    for (int i = blockIdx.x * 256 + threadIdx.x; i < BATCH * CH * 6;
         i += gridDim.x * 256) {
        int bc = i / 6, j = i - bc * 6;
        g_xs[(size_t)bc * NP + NN + j] = 0.0f;
    }

    const float4* xf4 = reinterpret_cast<const float4*>(x);
    const int npairs = TTNN / 64;                           // 43520 chunk pairs
    for (int p = gw; p < npairs; p += nwarps) {
        size_t base = (size_t)p * 192;
        float4 a0 = __ldcs(xf4 + base + lane);
        float4 b0 = __ldcs(xf4 + base + 32 + lane);
        float4 c0 = __ldcs(xf4 + base + 64 + lane);
        float4 a1 = __ldcs(xf4 + base + 96 + lane);
        float4 b1 = __ldcs(xf4 + base + 128 + lane);
        float4 c1 = __ldcs(xf4 + base + 160 + lane);
        float p00 = f4sum(a0), p01 = f4sum(b0), p02 = f4sum(c0);
        float p10 = f4sum(a1), p11 = f4sum(b1), p12 = f4sum(c1);
        int g = 3 * lane;
        float s0 = gran(p00, p01, p02, g) + gran(p00, p01, p02, g + 1)
                 + gran(p00, p01, p02, g + 2);
        float s1 = gran(p10, p11, p12, g) + gran(p10, p11, p12, g + 1)
                 + gran(p10, p11, p12, g + 2);
        int e0 = p * 64 + lane;
        int e1 = e0 + 32;
        int bc0 = e0 / NN, n0 = e0 - bc0 * NN;
        int bc1 = e1 / NN, n1 = e1 - bc1 * NN;
        g_xs[(size_t)bc0 * NP + n0] = s0;
        g_xs[(size_t)bc1 * NP + n1] = s1;
    }
}

// --------------- K_gemm1: ed[m][n] = tanh(sum_c Es[c][m] * xs[c][n])  (8x8)
__global__ void __launch_bounds__(256, 2) k_gemm1(const float* __restrict__ Es) {
    extern __shared__ float smf[];
    unsigned* es = reinterpret_cast<unsigned*>(smf);   // bf16x2 [128][88]
    float* xs = smf + CH * 88;                         // f32 [128][88]
    const int tid = threadIdx.x;
    const int b = blockIdx.x, h = blockIdx.y;

    for (int i = tid; i < CH * 88; i += 256) {
        int c = i / 88, mp = i - c * 88;
        int m0 = mp * 2;
        float f0 = 0.f, f1 = 0.f;
        if (m0 < NN) {
            float2 e = *reinterpret_cast<const float2*>(Es + c * NN + m0);
            f0 = e.x; f1 = e.y;
        }
        es[i] = bf_pack(f0, f1);
    }
    {
        const float* src = g_xs + (size_t)b * CH * NP + 88 * h;
        for (int i = tid; i < CH * 22; i += 256) {
            int c = i / 22, q = i - c * 22;
            reinterpret_cast<float4*>(xs)[c * 22 + q] =
                *reinterpret_cast<const float4*>(src + (size_t)c * NP + q * 4);
        }
    }
    __syncthreads();

    const int cell = tid;
    if (cell < 242) {
        const int smi = cell / 11, snj = cell - smi * 11;
        const int am = smi * 8, bn = snj * 8;
        u64t acc[8][4];
        #pragma unroll
        for (int i = 0; i < 8; i++)
            #pragma unroll
            for (int j = 0; j < 4; j++) acc[i][j] = 0ull;

        const unsigned* ep = es + (am >> 1);
        const float* bp = xs + bn;
        #pragma unroll 2
        for (int c = 0; c < CH; c++) {
            uint4 ev = *reinterpret_cast<const uint4*>(ep + c * 88);
            ulonglong2 b01 = *reinterpret_cast<const ulonglong2*>(bp + c * 88);
            ulonglong2 b23 = *reinterpret_cast<const ulonglong2*>(bp + c * 88 + 4);
            unsigned ew[4] = {ev.x, ev.y, ev.z, ev.w};
            #pragma unroll
            for (int q = 0; q < 4; q++) {
                u64t s0 = splat2u(ew[q] << 16);
                u64t s1 = splat2u(ew[q] & 0xFFFF0000u);
                ffma2(acc[2*q][0], s0, b01.x);  ffma2(acc[2*q][1], s0, b01.y);
                ffma2(acc[2*q][2], s0, b23.x);  ffma2(acc[2*q][3], s0, b23.y);
                ffma2(acc[2*q+1][0], s1, b01.x); ffma2(acc[2*q+1][1], s1, b01.y);
                ffma2(acc[2*q+1][2], s1, b23.x); ffma2(acc[2*q+1][3], s1, b23.y);
            }
        }

        #pragma unroll
        for (int mi = 0; mi < 8; mi++) {
            int m = am + mi;
            if (m < NN) {
                float f[8];
                #pragma unroll
                for (int j = 0; j < 4; j++) unpack2(f[2*j], f[2*j+1], acc[mi][j]);
                uint4 o;
                o.x = bf_pack(tanh_ap(f[0]), tanh_ap(f[1]));
                o.y = bf_pack(tanh_ap(f[2]), tanh_ap(f[3]));
                o.z = bf_pack(tanh_ap(f[4]), tanh_ap(f[5]));
                o.w = bf_pack(tanh_ap(f[6]), tanh_ap(f[7]));
                unsigned* dst = g_EdB + ((size_t)b * NN + m) * (NP/2) + ((88*h + bn) >> 1);
                *reinterpret_cast<uint4*>(dst) = o;
            }
        }
    }
}

// ---- K_adj: split-m symmetric GEMM2 (all 16 warps) + softmax + atomic accum
__global__ void __launch_bounds__(512, 1) k_adj() {
    extern __shared__ float sm[];
    float* ed = sm;                                          // [170][176] f32
    u64t* scratch = reinterpret_cast<u64t*>(sm);             // overlays ed (dead)
    __nv_bfloat16* sc = reinterpret_cast<__nv_bfloat16*>(sm + NN * NP);
    const int tid = threadIdx.x;
    const int b = blockIdx.x;

    // copy-in: bf16 -> f32 expansion
    {
        const uint4* src = reinterpret_cast<const uint4*>(g_EdB + (size_t)b * NN * (NP/2));
        for (int i = tid; i < (NN * NP) / 8; i += 512) {
            uint4 v = src[i];
            float4 f0, f1;
            f0.x = bf_lo(v.x); f0.y = bf_hi(v.x); f0.z = bf_lo(v.y); f0.w = bf_hi(v.y);
            f1.x = bf_lo(v.z); f1.y = bf_hi(v.z); f1.z = bf_lo(v.w); f1.w = bf_hi(v.w);
            reinterpret_cast<float4*>(ed)[2*i]   = f0;
            reinterpret_cast<float4*>(ed)[2*i+1] = f1;
        }
    }
    __syncthreads();

    const float scale = 0.08838834764831843f;                // 1/sqrt(128)
    const int half = tid >> 8;                               // m-range half
    const int cell = tid & 255;
    int n = 0, k = 0;
    u64t acc[8][4];
    #pragma unroll
    for (int i = 0; i < 8; i++)
        #pragma unroll
        for (int j = 0; j < 4; j++) acc[i][j] = 0ull;

    if (cell < 253) {
        int si = (int)((sqrtf(8.0f * (float)cell + 1.0f) - 1.0f) * 0.5f);
        while ((si + 1) * (si + 2) / 2 <= cell) si++;
        while (si * (si + 1) / 2 > cell) si--;
        const int sj = cell - si * (si + 1) / 2;
        n = si * 8; k = sj * 8;

        const int m0 = half ? 88 : 0;
        const int m1 = half ? NN : 88;
        #pragma unroll 2
        for (int m = m0; m < m1; m++) {
            const float* row = ed + m * NP;
            ulonglong2 a01 = *reinterpret_cast<const ulonglong2*>(row + n);
            ulonglong2 a23 = *reinterpret_cast<const ulonglong2*>(row + n + 4);
            float4 k0 = *reinterpret_cast<const float4*>(row + k);
            float4 k1 = *reinterpret_cast<const float4*>(row + k + 4);
            float kv[8] = {k0.x, k0.y, k0.z, k0.w, k1.x, k1.y, k1.z, k1.w};
            #pragma unroll
            for (int ki = 0; ki < 8; ki++) {
                u64t s = splat2(kv[ki]);
                ffma2(acc[ki][0], s, a01.x); ffma2(acc[ki][1], s, a01.y);
                ffma2(acc[ki][2], s, a23.x); ffma2(acc[ki][3], s, a23.y);
            }
        }
    }
    __syncthreads();                 // all ed reads done -> scratch may overlay

    // upper half publishes partials into scratch (cell-indexed, 32 u64 each)
    if (half == 1 && cell < 253) {
        u64t* dst = scratch + (size_t)cell * 32;
        #pragma unroll
        for (int i = 0; i < 8; i++)
            #pragma unroll
            for (int j = 0; j < 4; j++) dst[i * 4 + j] = acc[i][j];
    }
    __syncthreads();

    // lower half merges + epilogue -> bf16 scores (block + mirror)
    if (half == 0 && cell < 253) {
        const u64t* src = scratch + (size_t)cell * 32;
        #pragma unroll
        for (int i = 0; i < 8; i++)
            #pragma unroll
            for (int j = 0; j < 4; j++) add2(acc[i][j], src[i * 4 + j]);

        #pragma unroll
        for (int ki = 0; ki < 8; ki++) {
            int kk = k + ki;
            if (kk >= NN) continue;
            #pragma unroll
            for (int j = 0; j < 4; j++) {
                float v0, v1;
                unpack2(v0, v1, acc[ki][j]);
                int q0 = n + 2 * j, q1 = q0 + 1;
                __nv_bfloat16 h0 = __float2bfloat16(fmaxf(0.0f, v0 * scale));
                __nv_bfloat16 h1 = __float2bfloat16(fmaxf(0.0f, v1 * scale));
                if (q0 < NN) { sc[q0 * SCP + kk] = h0; sc[kk * SCP + q0] = h0; }
                if (q1 < NN) { sc[q1 * SCP + kk] = h1; sc[kk * SCP + q1] = h1; }
            }
        }
    }
    __syncthreads();

    // row softmax (scores in [0,~15.1] -> no max pass) + atomic accumulate
    const int wid = tid >> 5, lane = tid & 31;
    for (int nr = wid; nr < NN; nr += 16) {
        const __nv_bfloat16* row = sc + nr * SCP;
        float ssum = 0.0f;
        for (int kq = lane; kq < NN; kq += 32)
            ssum += __expf(__bfloat162float(row[kq]));
        #pragma unroll
        for (int o = 16; o; o >>= 1)
            ssum += __shfl_xor_sync(0xffffffffu, ssum, o);
        float inv = 1.0f / ssum;
        for (int kq = lane; kq < NN; kq += 32)
            atomicAdd(&g_Asum[nr * NN + kq],
                      __expf(__bfloat162float(row[kq])) * inv);
    }
}

// --------------------------------- K_thresh: threshold + self-restore g_Asum
__global__ void k_thresh(float* __restrict__ out) {
    int i = blockIdx.x * blockDim.x + threadIdx.x;
    if (i < NN * NN) {
        out[i] = (g_Asum[i] > 64.0f) ? 1.0f : 0.0f;          // mean > 0.5
        g_Asum[i] = 0.0f;                                    // restore for replay
    }
}

// ------------------------------------------------------------------- launcher
extern "C" void kernel_launch(void* const* d_in, const int* in_sizes, int n_in,
                              void* d_out, int out_size) {
    const float* x  = (const float*)d_in[0];   // [128,128,170,12] f32
    const float* Es = (const float*)d_in[1];   // [128,170] f32
    float* out = (float*)d_out;                // [170,170] f32

    cudaFuncSetAttribute(k_gemm1, cudaFuncAttributeMaxDynamicSharedMemorySize, SMEM_G1);
    cudaFuncSetAttribute(k_adj,   cudaFuncAttributeMaxDynamicSharedMemorySize, SMEM_A);

    k_load<<<1184, 256>>>(x);
    dim3 g1(BATCH, 2);
    k_gemm1<<<g1, 256, SMEM_G1>>>(Es);
    k_adj<<<BATCH, 512, SMEM_A>>>();
    k_thresh<<<(NN * NN + 255) / 256, 256>>>(out);
}